// round 4
// baseline (speedup 1.0000x reference)
#include <cuda_runtime.h>
#include <math.h>

#define T_TOKENS 8192
#define NEXP     64
#define KDIM     4096
#define TOPK     8

#define TM       64          // tokens per CTA
#define KC       32          // K-chunk
#define NTHREADS 256
#define GRID     (T_TOKENS / TM)   // 128 CTAs
#define NKT      (KDIM / KC)       // 128 K-iterations

// Deterministic aux-loss partials (no device allocation allowed)
__device__ float g_psum[GRID * NEXP];
__device__ int   g_cnt [GRID * NEXP];

__global__ __launch_bounds__(NTHREADS) void router_kernel(
    const float* __restrict__ H,   // [8192, 4096]
    const float* __restrict__ G,   // [64, 4096]
    float* __restrict__ out)       // [65536 w | 65536 idx | 1 loss]
{
    __shared__ float Hs[2][KC][TM];     // 16 KB, transposed [k][m]
    __shared__ float Gs[2][KC][NEXP];   // 16 KB, transposed [k][e]
    __shared__ int   s_cnt[NEXP];

    const int tid = threadIdx.x;
    const int m0  = blockIdx.x * TM;
    if (tid < NEXP) s_cnt[tid] = 0;

    // ---- global->smem load mapping: thread loads 2 float4 per tile ----
    const int c = tid & 7;     // float4 column within 32-float K-chunk
    const int r = tid >> 3;    // row 0..31 (and row r+32)

    // ---- compute micro-tile mapping: 4 tokens x 4 experts ----
    const int tx = tid & 15;   // expert group
    const int ty = tid >> 4;   // token group

    // fp64 master accumulators: error does not compound across tiles
    double accd[4][4];
#pragma unroll
    for (int i = 0; i < 4; i++)
#pragma unroll
        for (int j = 0; j < 4; j++) accd[i][j] = 0.0;

    float4 h0, h1, g0, g1;
    // prologue: load K-tile 0
    {
        const float* Hb = H + (size_t)(m0 + r) * KDIM;
        h0 = *(const float4*)(Hb + c * 4);
        h1 = *(const float4*)(Hb + (size_t)32 * KDIM + c * 4);
        const float* Gb = G + (size_t)r * KDIM;
        g0 = *(const float4*)(Gb + c * 4);
        g1 = *(const float4*)(Gb + (size_t)32 * KDIM + c * 4);
    }
    // store into buffer 0 (transposed)
    {
        Hs[0][c*4+0][r] = h0.x; Hs[0][c*4+1][r] = h0.y;
        Hs[0][c*4+2][r] = h0.z; Hs[0][c*4+3][r] = h0.w;
        Hs[0][c*4+0][r+32] = h1.x; Hs[0][c*4+1][r+32] = h1.y;
        Hs[0][c*4+2][r+32] = h1.z; Hs[0][c*4+3][r+32] = h1.w;
        Gs[0][c*4+0][r] = g0.x; Gs[0][c*4+1][r] = g0.y;
        Gs[0][c*4+2][r] = g0.z; Gs[0][c*4+3][r] = g0.w;
        Gs[0][c*4+0][r+32] = g1.x; Gs[0][c*4+1][r+32] = g1.y;
        Gs[0][c*4+2][r+32] = g1.z; Gs[0][c*4+3][r+32] = g1.w;
    }
    __syncthreads();

    for (int kt = 0; kt < NKT; kt++) {
        const int cbuf = kt & 1;
        const int nbuf = cbuf ^ 1;

        if (kt + 1 < NKT) {  // prefetch next tile into registers
            const int koff = (kt + 1) * KC;
            const float* Hb = H + (size_t)(m0 + r) * KDIM + koff;
            h0 = *(const float4*)(Hb + c * 4);
            h1 = *(const float4*)(Hb + (size_t)32 * KDIM + c * 4);
            const float* Gb = G + (size_t)r * KDIM + koff;
            g0 = *(const float4*)(Gb + c * 4);
            g1 = *(const float4*)(Gb + (size_t)32 * KDIM + c * 4);
        }

        // fresh fp32 tile partials: only 32-term chains -> tiny rounding error
        float t[4][4];
#pragma unroll
        for (int i = 0; i < 4; i++)
#pragma unroll
            for (int j = 0; j < 4; j++) t[i][j] = 0.0f;

#pragma unroll
        for (int k = 0; k < KC; k++) {
            float4 a = *(const float4*)&Hs[cbuf][k][ty * 4];
            float4 b = *(const float4*)&Gs[cbuf][k][tx * 4];
            t[0][0] += a.x * b.x; t[0][1] += a.x * b.y;
            t[0][2] += a.x * b.z; t[0][3] += a.x * b.w;
            t[1][0] += a.y * b.x; t[1][1] += a.y * b.y;
            t[1][2] += a.y * b.z; t[1][3] += a.y * b.w;
            t[2][0] += a.z * b.x; t[2][1] += a.z * b.y;
            t[2][2] += a.z * b.z; t[2][3] += a.z * b.w;
            t[3][0] += a.w * b.x; t[3][1] += a.w * b.y;
            t[3][2] += a.w * b.z; t[3][3] += a.w * b.w;
        }

        // fold tile partial into fp64 master accumulators
#pragma unroll
        for (int i = 0; i < 4; i++)
#pragma unroll
            for (int j = 0; j < 4; j++) accd[i][j] += (double)t[i][j];

        if (kt + 1 < NKT) {
            Hs[nbuf][c*4+0][r] = h0.x; Hs[nbuf][c*4+1][r] = h0.y;
            Hs[nbuf][c*4+2][r] = h0.z; Hs[nbuf][c*4+3][r] = h0.w;
            Hs[nbuf][c*4+0][r+32] = h1.x; Hs[nbuf][c*4+1][r+32] = h1.y;
            Hs[nbuf][c*4+2][r+32] = h1.z; Hs[nbuf][c*4+3][r+32] = h1.w;
            Gs[nbuf][c*4+0][r] = g0.x; Gs[nbuf][c*4+1][r] = g0.y;
            Gs[nbuf][c*4+2][r] = g0.z; Gs[nbuf][c*4+3][r] = g0.w;
            Gs[nbuf][c*4+0][r+32] = g1.x; Gs[nbuf][c*4+1][r+32] = g1.y;
            Gs[nbuf][c*4+2][r+32] = g1.z; Gs[nbuf][c*4+3][r+32] = g1.w;
            __syncthreads();
        }
    }
    __syncthreads();   // everyone done with both buffers before logits overlay

    // ---- logits to smem (reuse Hs memory: 64x64 floats = 16 KB) ----
    float* logits = &Hs[0][0][0];
#pragma unroll
    for (int i = 0; i < 4; i++)
#pragma unroll
        for (int j = 0; j < 4; j++)
            logits[(ty * 4 + i) * NEXP + tx * 4 + j] = (float)accd[i][j];
    __syncthreads();

    // ---- fused epilogue: one thread per token ----
    if (tid < TM) {
        const int m = tid;
        float row[NEXP];
        float mx = -1e30f;
#pragma unroll
        for (int e = 0; e < NEXP; e++) {
            row[e] = logits[m * NEXP + e];
            mx = fmaxf(mx, row[e]);
        }
        float s = 0.0f;
#pragma unroll
        for (int e = 0; e < NEXP; e++) { row[e] = expf(row[e] - mx); s += row[e]; }
        const float inv = 1.0f / s;
#pragma unroll
        for (int e = 0; e < NEXP; e++) {
            row[e] *= inv;
            logits[m * NEXP + e] = row[e];   // full softmax probs, for aux p-mean
        }

        // stable top-8 (descending, ties -> lower index), non-destructive
        float pv = 3.4e38f; int pidx = -1;
        float w[TOPK]; int idx[TOPK]; float wsum = 0.0f;
#pragma unroll
        for (int j = 0; j < TOPK; j++) {
            float bv = -1.0f; int bidx = -1;
#pragma unroll
            for (int e = 0; e < NEXP; e++) {
                const float v = row[e];
                const bool elig   = (v < pv) || (v == pv && e > pidx);
                const bool better = (v > bv) || (v == bv && e < bidx);
                if (elig && better) { bv = v; bidx = e; }
            }
            w[j] = bv; idx[j] = bidx; wsum += bv;
            pv = bv; pidx = bidx;
        }
        const float invw = 1.0f / wsum;
        const size_t gm = (size_t)(m0 + m) * TOPK;
#pragma unroll
        for (int j = 0; j < TOPK; j++) {
            out[gm + j] = w[j] * invw;
            out[(size_t)T_TOKENS * TOPK + gm + j] = (float)idx[j];
            atomicAdd(&s_cnt[idx[j]], 1);   // integer -> deterministic
        }
    }
    __syncthreads();

    // ---- per-block aux partials, fixed summation order (deterministic) ----
    if (tid < NEXP) {
        const int e = tid;
        float ps = 0.0f;
        for (int m = 0; m < TM; m++) ps += logits[m * NEXP + e];
        g_psum[blockIdx.x * NEXP + e] = ps;
        g_cnt [blockIdx.x * NEXP + e] = s_cnt[e];
    }
}

__global__ void finalize_kernel(float* __restrict__ out)
{
    __shared__ float fp[NEXP];
    const int e = threadIdx.x;   // 64 threads
    float ps = 0.0f; int cnt = 0;
    for (int b = 0; b < GRID; b++) {
        ps  += g_psum[b * NEXP + e];
        cnt += g_cnt [b * NEXP + e];
    }
    const float f = (float)cnt / (float)(T_TOKENS * TOPK);
    const float p = ps / (float)T_TOKENS;
    fp[e] = f * p;
    __syncthreads();
    if (e == 0) {
        float L = 0.0f;
        for (int i = 0; i < NEXP; i++) L += fp[i];
        out[(size_t)T_TOKENS * TOPK * 2] = (float)NEXP * L;
    }
}

extern "C" void kernel_launch(void* const* d_in, const int* in_sizes, int n_in,
                              void* d_out, int out_size)
{
    const float* H = (const float*)d_in[0];   // hidden_states [8192,4096]
    const float* G = (const float*)d_in[1];   // gate_w [64,4096]
    float* out = (float*)d_out;
    router_kernel<<<GRID, NTHREADS>>>(H, G, out);
    finalize_kernel<<<1, NEXP>>>(out);
}

// round 5
// speedup vs baseline: 1.2208x; 1.2208x over previous
#include <cuda_runtime.h>
#include <math.h>

#define T_TOKENS 8192
#define NEXP     64
#define KDIM     4096
#define TOPK     8

#define TM       64          // tokens per CTA
#define KC       32          // K-chunk
#define NTHREADS 256
#define GRID     (T_TOKENS / TM)   // 128 CTAs
#define NKT      (KDIM / KC)       // 128 K-iterations

// Deterministic aux-loss partials (no device allocation allowed)
__device__ float g_psum[GRID * NEXP];
__device__ int   g_cnt [GRID * NEXP];

__global__ __launch_bounds__(NTHREADS) void router_kernel(
    const float* __restrict__ H,   // [8192, 4096]
    const float* __restrict__ G,   // [64, 4096]
    float* __restrict__ out)       // [65536 w | 65536 idx | 1 loss]
{
    __shared__ float Hs[2][KC][TM];     // 16 KB, transposed [k][m]
    __shared__ float Gs[2][KC][NEXP];   // 16 KB, transposed [k][e]
    __shared__ int   s_cnt[NEXP];

    const int tid = threadIdx.x;
    const int m0  = blockIdx.x * TM;
    if (tid < NEXP) s_cnt[tid] = 0;

    // ---- global->smem load mapping: thread loads 2 float4 per tile ----
    const int c = tid & 7;     // float4 column within 32-float K-chunk
    const int r = tid >> 3;    // row 0..31 (and row r+32)

    // ---- compute micro-tile mapping: 4 tokens x 4 experts ----
    const int tx = tid & 15;   // expert group
    const int ty = tid >> 4;   // token group

    // Kahan-compensated fp32 master accumulators (fma pipe, not fp64 pipe)
    float acc[4][4], cmp[4][4];
#pragma unroll
    for (int i = 0; i < 4; i++)
#pragma unroll
        for (int j = 0; j < 4; j++) { acc[i][j] = 0.0f; cmp[i][j] = 0.0f; }

    float4 h0, h1, g0, g1;
    // prologue: load K-tile 0
    {
        const float* Hb = H + (size_t)(m0 + r) * KDIM;
        h0 = *(const float4*)(Hb + c * 4);
        h1 = *(const float4*)(Hb + (size_t)32 * KDIM + c * 4);
        const float* Gb = G + (size_t)r * KDIM;
        g0 = *(const float4*)(Gb + c * 4);
        g1 = *(const float4*)(Gb + (size_t)32 * KDIM + c * 4);
    }
    // store into buffer 0 (transposed)
    {
        Hs[0][c*4+0][r] = h0.x; Hs[0][c*4+1][r] = h0.y;
        Hs[0][c*4+2][r] = h0.z; Hs[0][c*4+3][r] = h0.w;
        Hs[0][c*4+0][r+32] = h1.x; Hs[0][c*4+1][r+32] = h1.y;
        Hs[0][c*4+2][r+32] = h1.z; Hs[0][c*4+3][r+32] = h1.w;
        Gs[0][c*4+0][r] = g0.x; Gs[0][c*4+1][r] = g0.y;
        Gs[0][c*4+2][r] = g0.z; Gs[0][c*4+3][r] = g0.w;
        Gs[0][c*4+0][r+32] = g1.x; Gs[0][c*4+1][r+32] = g1.y;
        Gs[0][c*4+2][r+32] = g1.z; Gs[0][c*4+3][r+32] = g1.w;
    }
    __syncthreads();

    for (int kt = 0; kt < NKT; kt++) {
        const int cbuf = kt & 1;
        const int nbuf = cbuf ^ 1;

        if (kt + 1 < NKT) {  // prefetch next tile into registers
            const int koff = (kt + 1) * KC;
            const float* Hb = H + (size_t)(m0 + r) * KDIM + koff;
            h0 = *(const float4*)(Hb + c * 4);
            h1 = *(const float4*)(Hb + (size_t)32 * KDIM + c * 4);
            const float* Gb = G + (size_t)r * KDIM + koff;
            g0 = *(const float4*)(Gb + c * 4);
            g1 = *(const float4*)(Gb + (size_t)32 * KDIM + c * 4);
        }

        // fresh fp32 tile partials: only 32-term chains -> tiny rounding error
        float t[4][4];
#pragma unroll
        for (int i = 0; i < 4; i++)
#pragma unroll
            for (int j = 0; j < 4; j++) t[i][j] = 0.0f;

#pragma unroll
        for (int k = 0; k < KC; k++) {
            float4 a = *(const float4*)&Hs[cbuf][k][ty * 4];
            float4 b = *(const float4*)&Gs[cbuf][k][tx * 4];
            t[0][0] += a.x * b.x; t[0][1] += a.x * b.y;
            t[0][2] += a.x * b.z; t[0][3] += a.x * b.w;
            t[1][0] += a.y * b.x; t[1][1] += a.y * b.y;
            t[1][2] += a.y * b.z; t[1][3] += a.y * b.w;
            t[2][0] += a.z * b.x; t[2][1] += a.z * b.y;
            t[2][2] += a.z * b.z; t[2][3] += a.z * b.w;
            t[3][0] += a.w * b.x; t[3][1] += a.w * b.y;
            t[3][2] += a.w * b.z; t[3][3] += a.w * b.w;
        }

        // Kahan fold of tile partial into fp32 masters.
        // __f*_rn intrinsics block fast-math reassociation/contraction.
#pragma unroll
        for (int i = 0; i < 4; i++)
#pragma unroll
            for (int j = 0; j < 4; j++) {
                const float y = __fsub_rn(t[i][j], cmp[i][j]);
                const float u = __fadd_rn(acc[i][j], y);
                cmp[i][j] = __fsub_rn(__fsub_rn(u, acc[i][j]), y);
                acc[i][j] = u;
            }

        if (kt + 1 < NKT) {
            Hs[nbuf][c*4+0][r] = h0.x; Hs[nbuf][c*4+1][r] = h0.y;
            Hs[nbuf][c*4+2][r] = h0.z; Hs[nbuf][c*4+3][r] = h0.w;
            Hs[nbuf][c*4+0][r+32] = h1.x; Hs[nbuf][c*4+1][r+32] = h1.y;
            Hs[nbuf][c*4+2][r+32] = h1.z; Hs[nbuf][c*4+3][r+32] = h1.w;
            Gs[nbuf][c*4+0][r] = g0.x; Gs[nbuf][c*4+1][r] = g0.y;
            Gs[nbuf][c*4+2][r] = g0.z; Gs[nbuf][c*4+3][r] = g0.w;
            Gs[nbuf][c*4+0][r+32] = g1.x; Gs[nbuf][c*4+1][r+32] = g1.y;
            Gs[nbuf][c*4+2][r+32] = g1.z; Gs[nbuf][c*4+3][r+32] = g1.w;
            __syncthreads();
        }
    }
    __syncthreads();   // everyone done with both buffers before logits overlay

    // ---- logits to smem (reuse Hs memory: 64x64 floats = 16 KB) ----
    float* logits = &Hs[0][0][0];
#pragma unroll
    for (int i = 0; i < 4; i++)
#pragma unroll
        for (int j = 0; j < 4; j++)
            logits[(ty * 4 + i) * NEXP + tx * 4 + j] = acc[i][j];
    __syncthreads();

    // ---- fused epilogue: one thread per token ----
    if (tid < TM) {
        const int m = tid;
        float row[NEXP];
        float mx = -1e30f;
#pragma unroll
        for (int e = 0; e < NEXP; e++) {
            row[e] = logits[m * NEXP + e];
            mx = fmaxf(mx, row[e]);
        }
        float s = 0.0f;
#pragma unroll
        for (int e = 0; e < NEXP; e++) { row[e] = expf(row[e] - mx); s += row[e]; }
        const float inv = 1.0f / s;
#pragma unroll
        for (int e = 0; e < NEXP; e++) {
            row[e] *= inv;
            logits[m * NEXP + e] = row[e];   // full softmax probs, for aux p-mean
        }

        // stable top-8 (descending, ties -> lower index), non-destructive
        float pv = 3.4e38f; int pidx = -1;
        float w[TOPK]; int idx[TOPK]; float wsum = 0.0f;
#pragma unroll
        for (int j = 0; j < TOPK; j++) {
            float bv = -1.0f; int bidx = -1;
#pragma unroll
            for (int e = 0; e < NEXP; e++) {
                const float v = row[e];
                const bool elig   = (v < pv) || (v == pv && e > pidx);
                const bool better = (v > bv) || (v == bv && e < bidx);
                if (elig && better) { bv = v; bidx = e; }
            }
            w[j] = bv; idx[j] = bidx; wsum += bv;
            pv = bv; pidx = bidx;
        }
        const float invw = 1.0f / wsum;
        const size_t gm = (size_t)(m0 + m) * TOPK;
#pragma unroll
        for (int j = 0; j < TOPK; j++) {
            out[gm + j] = w[j] * invw;
            out[(size_t)T_TOKENS * TOPK + gm + j] = (float)idx[j];
            atomicAdd(&s_cnt[idx[j]], 1);   // integer -> deterministic
        }
    }
    __syncthreads();

    // ---- per-block aux partials, fixed summation order (deterministic) ----
    if (tid < NEXP) {
        const int e = tid;
        float ps = 0.0f;
        for (int m = 0; m < TM; m++) ps += logits[m * NEXP + e];
        g_psum[blockIdx.x * NEXP + e] = ps;
        g_cnt [blockIdx.x * NEXP + e] = s_cnt[e];
    }
}

#define FIN_THREADS 256
#define FIN_PARTS   (FIN_THREADS / NEXP)        // 4 partial-summers per expert
#define FIN_BPP     (GRID / FIN_PARTS)          // 32 blocks per partial

__global__ __launch_bounds__(FIN_THREADS) void finalize_kernel(float* __restrict__ out)
{
    __shared__ float ps_s[FIN_PARTS][NEXP];
    __shared__ int   ct_s[FIN_PARTS][NEXP];
    __shared__ float fp[NEXP];

    const int e    = threadIdx.x & (NEXP - 1);
    const int part = threadIdx.x >> 6;          // 0..3

    float ps = 0.0f; int cnt = 0;
#pragma unroll 4
    for (int b = part * FIN_BPP; b < (part + 1) * FIN_BPP; b++) {
        ps  += g_psum[b * NEXP + e];
        cnt += g_cnt [b * NEXP + e];
    }
    ps_s[part][e] = ps;
    ct_s[part][e] = cnt;
    __syncthreads();

    if (part == 0) {
        // fixed-order combine -> deterministic
        float tot = ps_s[0][e] + ps_s[1][e] + ps_s[2][e] + ps_s[3][e];
        int   ctt = ct_s[0][e] + ct_s[1][e] + ct_s[2][e] + ct_s[3][e];
        const float f = (float)ctt / (float)(T_TOKENS * TOPK);
        const float p = tot / (float)T_TOKENS;
        fp[e] = f * p;
    }
    __syncthreads();
    if (threadIdx.x == 0) {
        float L = 0.0f;
#pragma unroll
        for (int i = 0; i < NEXP; i++) L += fp[i];
        out[(size_t)T_TOKENS * TOPK * 2] = (float)NEXP * L;
    }
}

extern "C" void kernel_launch(void* const* d_in, const int* in_sizes, int n_in,
                              void* d_out, int out_size)
{
    const float* H = (const float*)d_in[0];   // hidden_states [8192,4096]
    const float* G = (const float*)d_in[1];   // gate_w [64,4096]
    float* out = (float*)d_out;
    router_kernel<<<GRID, NTHREADS>>>(H, G, out);
    finalize_kernel<<<1, FIN_THREADS>>>(out);
}

// round 7
// speedup vs baseline: 1.7389x; 1.4244x over previous
#include <cuda_runtime.h>
#include <math.h>

#define T_TOKENS 8192
#define NEXP     64
#define KDIM     4096
#define TOPK     8

#define TM       64          // tokens per CTA
#define KC       32          // K-chunk
#define NTHREADS 512         // 16 warps -> 4 per SMSP (latency hiding)
#define GRID     (T_TOKENS / TM)   // 128 CTAs
#define NKT      (KDIM / KC)       // 128 K-iterations

// Deterministic aux-loss partials (no device allocation allowed)
__device__ float g_psum[GRID * NEXP];
__device__ int   g_cnt [GRID * NEXP];

__global__ __launch_bounds__(NTHREADS) void router_kernel(
    const float* __restrict__ H,   // [8192, 4096]
    const float* __restrict__ G,   // [64, 4096]
    float* __restrict__ out)       // [65536 w | 65536 idx | 1 loss]
{
    __shared__ float Hs[2][KC][TM];     // 16 KB, transposed [k][m]
    __shared__ float Gs[2][KC][NEXP];   // 16 KB, transposed [k][e]
    __shared__ int   s_cnt[NEXP];

    const int tid = threadIdx.x;
    const int m0  = blockIdx.x * TM;
    if (tid < NEXP) s_cnt[tid] = 0;

    // ---- global->smem load mapping: thread loads 1 float4 of H + 1 of G ----
    const int c = tid & 7;     // float4 column within 32-float K-chunk
    const int r = tid >> 3;    // row 0..63 (token row for H, expert row for G)

    // ---- compute micro-tile mapping: 2 tokens x 4 experts ----
    const int tx = tid & 15;   // expert group (4 experts)
    const int ty = tid >> 4;   // token group 0..31 (2 tokens)

    // Kahan-compensated fp32 master accumulators (fma pipe)
    float acc[2][4], cmp[2][4];
#pragma unroll
    for (int i = 0; i < 2; i++)
#pragma unroll
        for (int j = 0; j < 4; j++) { acc[i][j] = 0.0f; cmp[i][j] = 0.0f; }

    float4 h0, g0;
    // prologue: load K-tile 0
    {
        h0 = *(const float4*)(H + (size_t)(m0 + r) * KDIM + c * 4);
        g0 = *(const float4*)(G + (size_t)r * KDIM + c * 4);
    }
    // store into buffer 0 (transposed)
    {
        Hs[0][c*4+0][r] = h0.x; Hs[0][c*4+1][r] = h0.y;
        Hs[0][c*4+2][r] = h0.z; Hs[0][c*4+3][r] = h0.w;
        Gs[0][c*4+0][r] = g0.x; Gs[0][c*4+1][r] = g0.y;
        Gs[0][c*4+2][r] = g0.z; Gs[0][c*4+3][r] = g0.w;
    }
    __syncthreads();

    for (int kt = 0; kt < NKT; kt++) {
        const int cbuf = kt & 1;
        const int nbuf = cbuf ^ 1;

        if (kt + 1 < NKT) {  // prefetch next tile into registers
            const int koff = (kt + 1) * KC;
            h0 = *(const float4*)(H + (size_t)(m0 + r) * KDIM + koff + c * 4);
            g0 = *(const float4*)(G + (size_t)r * KDIM + koff + c * 4);
        }

        // fresh fp32 tile partials: only 32-term chains -> tiny rounding error
        float t[2][4];
#pragma unroll
        for (int i = 0; i < 2; i++)
#pragma unroll
            for (int j = 0; j < 4; j++) t[i][j] = 0.0f;

#pragma unroll
        for (int k = 0; k < KC; k++) {
            const float2 a = *(const float2*)&Hs[cbuf][k][ty * 2];
            const float4 b = *(const float4*)&Gs[cbuf][k][tx * 4];
            t[0][0] += a.x * b.x; t[0][1] += a.x * b.y;
            t[0][2] += a.x * b.z; t[0][3] += a.x * b.w;
            t[1][0] += a.y * b.x; t[1][1] += a.y * b.y;
            t[1][2] += a.y * b.z; t[1][3] += a.y * b.w;
        }

        // Kahan fold of tile partial into fp32 masters.
        // __f*_rn intrinsics block fast-math reassociation/contraction.
#pragma unroll
        for (int i = 0; i < 2; i++)
#pragma unroll
            for (int j = 0; j < 4; j++) {
                const float y = __fsub_rn(t[i][j], cmp[i][j]);
                const float u = __fadd_rn(acc[i][j], y);
                cmp[i][j] = __fsub_rn(__fsub_rn(u, acc[i][j]), y);
                acc[i][j] = u;
            }

        if (kt + 1 < NKT) {
            Hs[nbuf][c*4+0][r] = h0.x; Hs[nbuf][c*4+1][r] = h0.y;
            Hs[nbuf][c*4+2][r] = h0.z; Hs[nbuf][c*4+3][r] = h0.w;
            Gs[nbuf][c*4+0][r] = g0.x; Gs[nbuf][c*4+1][r] = g0.y;
            Gs[nbuf][c*4+2][r] = g0.z; Gs[nbuf][c*4+3][r] = g0.w;
            __syncthreads();
        }
    }
    __syncthreads();   // everyone done with both buffers before logits overlay

    // ---- logits to smem (reuse Hs memory: 64x64 floats = 16 KB) ----
    float* logits = &Hs[0][0][0];
#pragma unroll
    for (int i = 0; i < 2; i++)
#pragma unroll
        for (int j = 0; j < 4; j++)
            logits[(ty * 2 + i) * NEXP + tx * 4 + j] = acc[i][j];
    __syncthreads();

    // ---- fused epilogue: one thread per token ----
    if (tid < TM) {
        const int m = tid;
        float row[NEXP];
        float mx = -1e30f;
#pragma unroll
        for (int e = 0; e < NEXP; e++) {
            row[e] = logits[m * NEXP + e];
            mx = fmaxf(mx, row[e]);
        }
        float s = 0.0f;
#pragma unroll
        for (int e = 0; e < NEXP; e++) { row[e] = expf(row[e] - mx); s += row[e]; }
        const float inv = 1.0f / s;
#pragma unroll
        for (int e = 0; e < NEXP; e++) {
            row[e] *= inv;
            logits[m * NEXP + e] = row[e];   // full softmax probs, for aux p-mean
        }

        // stable top-8 (descending, ties -> lower index), non-destructive
        float pv = 3.4e38f; int pidx = -1;
        float w[TOPK]; int idx[TOPK]; float wsum = 0.0f;
#pragma unroll
        for (int j = 0; j < TOPK; j++) {
            float bv = -1.0f; int bidx = -1;
#pragma unroll
            for (int e = 0; e < NEXP; e++) {
                const float v = row[e];
                const bool elig   = (v < pv) || (v == pv && e > pidx);
                const bool better = (v > bv) || (v == bv && e < bidx);
                if (elig && better) { bv = v; bidx = e; }
            }
            w[j] = bv; idx[j] = bidx; wsum += bv;
            pv = bv; pidx = bidx;
        }
        const float invw = 1.0f / wsum;
        const size_t gm = (size_t)(m0 + m) * TOPK;
#pragma unroll
        for (int j = 0; j < TOPK; j++) {
            out[gm + j] = w[j] * invw;
            out[(size_t)T_TOKENS * TOPK + gm + j] = (float)idx[j];
            atomicAdd(&s_cnt[idx[j]], 1);   // integer -> deterministic
        }
    }
    __syncthreads();

    // ---- per-block aux partials, fixed summation order (deterministic) ----
    if (tid < NEXP) {
        const int e = tid;
        float ps = 0.0f;
        for (int m = 0; m < TM; m++) ps += logits[m * NEXP + e];
        g_psum[blockIdx.x * NEXP + e] = ps;
        g_cnt [blockIdx.x * NEXP + e] = s_cnt[e];
    }
}

#define FIN_THREADS 256
#define FIN_PARTS   (FIN_THREADS / NEXP)        // 4 partial-summers per expert
#define FIN_BPP     (GRID / FIN_PARTS)          // 32 blocks per partial

__global__ __launch_bounds__(FIN_THREADS) void finalize_kernel(float* __restrict__ out)
{
    __shared__ float ps_s[FIN_PARTS][NEXP];
    __shared__ int   ct_s[FIN_PARTS][NEXP];
    __shared__ float fp[NEXP];

    const int e    = threadIdx.x & (NEXP - 1);
    const int part = threadIdx.x >> 6;          // 0..3

    float ps = 0.0f; int cnt = 0;
#pragma unroll 4
    for (int b = part * FIN_BPP; b < (part + 1) * FIN_BPP; b++) {
        ps  += g_psum[b * NEXP + e];
        cnt += g_cnt [b * NEXP + e];
    }
    ps_s[part][e] = ps;
    ct_s[part][e] = cnt;
    __syncthreads();

    if (part == 0) {
        // fixed-order combine -> deterministic
        float tot = ps_s[0][e] + ps_s[1][e] + ps_s[2][e] + ps_s[3][e];
        int   ctt = ct_s[0][e] + ct_s[1][e] + ct_s[2][e] + ct_s[3][e];
        const float f = (float)ctt / (float)(T_TOKENS * TOPK);
        const float p = tot / (float)T_TOKENS;
        fp[e] = f * p;
    }
    __syncthreads();
    if (threadIdx.x == 0) {
        float L = 0.0f;
#pragma unroll
        for (int i = 0; i < NEXP; i++) L += fp[i];
        out[(size_t)T_TOKENS * TOPK * 2] = (float)NEXP * L;
    }
}

extern "C" void kernel_launch(void* const* d_in, const int* in_sizes, int n_in,
                              void* d_out, int out_size)
{
    const float* H = (const float*)d_in[0];   // hidden_states [8192,4096]
    const float* G = (const float*)d_in[1];   // gate_w [64,4096]
    float* out = (float*)d_out;
    router_kernel<<<GRID, NTHREADS>>>(H, G, out);
    finalize_kernel<<<1, FIN_THREADS>>>(out);
}

// round 16
// speedup vs baseline: 1.7419x; 1.0017x over previous
#include <cuda_runtime.h>
#include <cstdint>
#include <math.h>

#define T_TOKENS 8192
#define NEXP     64
#define KDIM     4096
#define TOPK     8

#define TM       64                   // tokens per CTA
#define KC       64                   // K per stage
#define NSTAGES  (KDIM / KC)          // 64
#define NTHREADS 256
#define GRID     (T_TOKENS / TM)      // 128 CTAs (1 wave)

#define ROWW       66                 // words per packed row (64 + 2 pad, even -> 8B aligned pairs)
#define TILE_WORDS (64 * ROWW)        // one 64-row tile
#define BUF_WORDS  (4 * TILE_WORDS)   // Ah, Al, Bh, Bl
#define SMEM_BYTES (2 * BUF_WORDS * 4)
#define LROW       66                 // logits row stride (reuse smem)

// Deterministic aux-loss partials
__device__ float g_psum[GRID * NEXP];
__device__ int   g_cnt [GRID * NEXP];

// packed addr: pairs (k, k+4) adjacent so {b0,b1}/{a0,a2} are one 64-bit LDS
__device__ __forceinline__ int paddr(int row, int k) {
    return row * ROWW + ((k >> 3) << 3) + ((k & 3) << 1) + ((k >> 2) & 1);
}

__device__ __forceinline__ void tf32split(float x, uint32_t& hi, uint32_t& lo) {
    uint32_t xb = __float_as_uint(x);
    hi = xb & 0xFFFFE000u;
    float r = __fsub_rn(x, __uint_as_float(hi));
    lo = __float_as_uint(r) & 0xFFFFE000u;
}

__device__ __forceinline__ void mma_tf32(float* c, const uint32_t* a, uint32_t b0, uint32_t b1) {
    asm volatile(
        "mma.sync.aligned.m16n8k8.row.col.f32.tf32.tf32.f32 "
        "{%0,%1,%2,%3}, {%4,%5,%6,%7}, {%8,%9}, {%0,%1,%2,%3};"
        : "+f"(c[0]), "+f"(c[1]), "+f"(c[2]), "+f"(c[3])
        : "r"(a[0]), "r"(a[1]), "r"(a[2]), "r"(a[3]), "r"(b0), "r"(b1));
}

__device__ __forceinline__ void store_split4(uint32_t* th, uint32_t* tl,
                                             int row, int c4, float4 v) {
    uint32_t hi, lo;
    const int k = c4 * 4;
    tf32split(v.x, hi, lo); th[paddr(row, k+0)] = hi; tl[paddr(row, k+0)] = lo;
    tf32split(v.y, hi, lo); th[paddr(row, k+1)] = hi; tl[paddr(row, k+1)] = lo;
    tf32split(v.z, hi, lo); th[paddr(row, k+2)] = hi; tl[paddr(row, k+2)] = lo;
    tf32split(v.w, hi, lo); th[paddr(row, k+3)] = hi; tl[paddr(row, k+3)] = lo;
}

// -----------------------------------------------------------------------------
__global__ __launch_bounds__(NTHREADS, 1) void router_kernel(
    const float* __restrict__ H,   // [8192, 4096]
    const float* __restrict__ G,   // [64, 4096]
    float* __restrict__ out)       // [65536 w | 65536 idx | 1 loss]
{
    extern __shared__ uint32_t smem[];
    __shared__ int s_cnt[NEXP];

    const int tid  = threadIdx.x;
    const int warp = tid >> 5;
    const int lane = tid & 31;
    const int mw   = warp >> 1;          // 0..3 : rows mw*16
    const int nw   = warp & 1;           // 0..1 : cols nw*32
    const int g    = lane >> 2;          // 0..7
    const int t    = lane & 3;           // 0..3
    const int m0   = blockIdx.x * TM;

    if (tid < NEXP) s_cnt[tid] = 0;

    // per-thread fill mapping (same every stage): 4 float4 of H, 4 of G
    int rowF[4], c4F[4];
#pragma unroll
    for (int i = 0; i < 4; i++) {
        const int idx4 = tid + i * NTHREADS;   // < 1024
        rowF[i] = idx4 >> 4;
        c4F[i]  = idx4 & 15;
    }

    // ---- prologue: fill stage 0 into buffer 0 ----
    {
        uint32_t* Ah = smem;
        uint32_t* Al = smem + TILE_WORDS;
        uint32_t* Bh = smem + 2 * TILE_WORDS;
        uint32_t* Bl = smem + 3 * TILE_WORDS;
#pragma unroll
        for (int i = 0; i < 4; i++) {
            float4 v = *(const float4*)(H + (size_t)(m0 + rowF[i]) * KDIM + c4F[i] * 4);
            store_split4(Ah, Al, rowF[i], c4F[i], v);
            float4 u = *(const float4*)(G + (size_t)rowF[i] * KDIM + c4F[i] * 4);
            store_split4(Bh, Bl, rowF[i], c4F[i], u);
        }
    }
    __syncthreads();

    float C[4][4], M[4][4], CK[4][4];
#pragma unroll
    for (int T = 0; T < 4; T++)
#pragma unroll
        for (int i = 0; i < 4; i++) { C[T][i] = 0.0f; M[T][i] = 0.0f; CK[T][i] = 0.0f; }

    const int aBase0 = (mw * 16 + g) * ROWW;     // A row g of slab
    const int aBase1 = aBase0 + 8 * ROWW;        // A row g+8
    const int bBase  = (nw * 32 + g) * ROWW;     // B tile 0 (n = nw*32 + T*8 + g)

    float4 hreg[4], greg[4];

    for (int st = 0; st < NSTAGES; st++) {
        const int cur = st & 1;
        const uint32_t* bufc = smem + cur * BUF_WORDS;

        if (st + 1 < NSTAGES) {   // prefetch next stage into registers
            const int koff = (st + 1) * KC;
#pragma unroll
            for (int i = 0; i < 4; i++) {
                hreg[i] = *(const float4*)(H + (size_t)(m0 + rowF[i]) * KDIM + koff + c4F[i] * 4);
                greg[i] = *(const float4*)(G + (size_t)rowF[i] * KDIM + koff + c4F[i] * 4);
            }
        }

        // ---- compute: 8 k8-chunks ----
        const uint32_t* Ah = bufc;
        const uint32_t* Al = bufc + TILE_WORDS;
        const uint32_t* Bh = bufc + 2 * TILE_WORDS;
        const uint32_t* Bl = bufc + 3 * TILE_WORDS;
#pragma unroll
        for (int ch = 0; ch < 8; ch++) {
            const int co = ch * 8 + t * 2;
            uint32_t aH[4], aL[4];
            {   // {a0,a2} from row g ; {a1,a3} from row g+8
                const uint2 p0 = *(const uint2*)(Ah + aBase0 + co);
                const uint2 p1 = *(const uint2*)(Ah + aBase1 + co);
                aH[0] = p0.x; aH[2] = p0.y; aH[1] = p1.x; aH[3] = p1.y;
                const uint2 q0 = *(const uint2*)(Al + aBase0 + co);
                const uint2 q1 = *(const uint2*)(Al + aBase1 + co);
                aL[0] = q0.x; aL[2] = q0.y; aL[1] = q1.x; aL[3] = q1.y;
            }
#pragma unroll
            for (int T = 0; T < 4; T++) {
                const int bo = bBase + T * 8 * ROWW + co;
                const uint2 bh = *(const uint2*)(Bh + bo);   // {b0 (k=t), b1 (k=t+4)}
                const uint2 bl = *(const uint2*)(Bl + bo);
                mma_tf32(C[T], aH, bh.x, bh.y);   // hh
                mma_tf32(C[T], aH, bl.x, bl.y);   // hl
                mma_tf32(C[T], aL, bh.x, bh.y);   // lh
            }
        }

        // Kahan-fold stage partial C into masters EVERY stage: caps the fp32
        // accumulation chain at ~24 MMA steps (stage) + ~2eps (Kahan masters).
        // __f*_rn intrinsics block reassociation/contraction.
#pragma unroll
        for (int T = 0; T < 4; T++)
#pragma unroll
            for (int i = 0; i < 4; i++) {
                const float y = __fsub_rn(C[T][i], CK[T][i]);
                const float u = __fadd_rn(M[T][i], y);
                CK[T][i] = __fsub_rn(__fsub_rn(u, M[T][i]), y);
                M[T][i] = u;
                C[T][i] = 0.0f;
            }

        // ---- store prefetched stage into the other buffer ----
        if (st + 1 < NSTAGES) {
            uint32_t* nb = smem + (cur ^ 1) * BUF_WORDS;
#pragma unroll
            for (int i = 0; i < 4; i++) {
                store_split4(nb, nb + TILE_WORDS, rowF[i], c4F[i], hreg[i]);
                store_split4(nb + 2 * TILE_WORDS, nb + 3 * TILE_WORDS, rowF[i], c4F[i], greg[i]);
            }
        }
        __syncthreads();
    }

    // ---- scatter masters to smem logits [64][LROW] (reuse buffers) ----
    float* logits = (float*)smem;
    {
        const int r0 = mw * 16 + g;
        const int r1 = r0 + 8;
#pragma unroll
        for (int T = 0; T < 4; T++) {
            const int cb = nw * 32 + T * 8 + 2 * t;
            logits[r0 * LROW + cb]     = M[T][0];
            logits[r0 * LROW + cb + 1] = M[T][1];
            logits[r1 * LROW + cb]     = M[T][2];
            logits[r1 * LROW + cb + 1] = M[T][3];
        }
    }
    __syncthreads();

    // ---- fused epilogue: one thread per token ----
    if (tid < TM) {
        float row[NEXP];
        float mx = -1e30f;
#pragma unroll
        for (int e = 0; e < NEXP; e++) {
            row[e] = logits[tid * LROW + e];
            mx = fmaxf(mx, row[e]);
        }
        float s = 0.0f;
#pragma unroll
        for (int e = 0; e < NEXP; e++) { row[e] = expf(row[e] - mx); s += row[e]; }
        const float inv = 1.0f / s;
#pragma unroll
        for (int e = 0; e < NEXP; e++) {
            row[e] *= inv;
            logits[tid * LROW + e] = row[e];   // softmax probs, for aux p-mean
        }

        // stable top-8 (descending, ties -> lower index)
        float pv = 3.4e38f; int pidx = -1;
        float w[TOPK]; int idx[TOPK]; float wsum = 0.0f;
#pragma unroll
        for (int j = 0; j < TOPK; j++) {
            float bv = -1.0f; int bidx = -1;
#pragma unroll
            for (int e = 0; e < NEXP; e++) {
                const float v = row[e];
                const bool elig   = (v < pv) || (v == pv && e > pidx);
                const bool better = (v > bv) || (v == bv && e < bidx);
                if (elig && better) { bv = v; bidx = e; }
            }
            w[j] = bv; idx[j] = bidx; wsum += bv;
            pv = bv; pidx = bidx;
        }
        const float invw = 1.0f / wsum;
        const size_t gm = (size_t)(m0 + tid) * TOPK;
#pragma unroll
        for (int j = 0; j < TOPK; j++) {
            out[gm + j] = w[j] * invw;
            out[(size_t)T_TOKENS * TOPK + gm + j] = (float)idx[j];
            atomicAdd(&s_cnt[idx[j]], 1);   // integer -> deterministic
        }
    }
    __syncthreads();

    // per-block aux partials, fixed summation order (deterministic)
    if (tid < NEXP) {
        const int e = tid;
        float ps = 0.0f;
        for (int m = 0; m < TM; m++) ps += logits[m * LROW + e];
        g_psum[blockIdx.x * NEXP + e] = ps;
        g_cnt [blockIdx.x * NEXP + e] = s_cnt[e];
    }
}

#define FIN_THREADS 256
#define FIN_PARTS   (FIN_THREADS / NEXP)        // 4
#define FIN_BPP     (GRID / FIN_PARTS)          // 32

__global__ __launch_bounds__(FIN_THREADS) void finalize_kernel(float* __restrict__ out)
{
    __shared__ float ps_s[FIN_PARTS][NEXP];
    __shared__ int   ct_s[FIN_PARTS][NEXP];
    __shared__ float fp[NEXP];

    const int e    = threadIdx.x & (NEXP - 1);
    const int part = threadIdx.x >> 6;

    float ps = 0.0f; int cnt = 0;
#pragma unroll 4
    for (int b = part * FIN_BPP; b < (part + 1) * FIN_BPP; b++) {
        ps  += g_psum[b * NEXP + e];
        cnt += g_cnt [b * NEXP + e];
    }
    ps_s[part][e] = ps;
    ct_s[part][e] = cnt;
    __syncthreads();

    if (part == 0) {
        float tot = ps_s[0][e] + ps_s[1][e] + ps_s[2][e] + ps_s[3][e];
        int   ctt = ct_s[0][e] + ct_s[1][e] + ct_s[2][e] + ct_s[3][e];
        const float f = (float)ctt / (float)(T_TOKENS * TOPK);
        const float p = tot / (float)T_TOKENS;
        fp[e] = f * p;
    }
    __syncthreads();
    if (threadIdx.x == 0) {
        float L = 0.0f;
#pragma unroll
        for (int i = 0; i < NEXP; i++) L += fp[i];
        out[(size_t)T_TOKENS * TOPK * 2] = (float)NEXP * L;
    }
}

extern "C" void kernel_launch(void* const* d_in, const int* in_sizes, int n_in,
                              void* d_out, int out_size)
{
    const float* H = (const float*)d_in[0];
    const float* G = (const float*)d_in[1];
    float* out = (float*)d_out;
    cudaFuncSetAttribute(router_kernel, cudaFuncAttributeMaxDynamicSharedMemorySize, SMEM_BYTES);
    router_kernel<<<GRID, NTHREADS, SMEM_BYTES>>>(H, G, out);
    finalize_kernel<<<1, FIN_THREADS>>>(out);
}